// round 12
// baseline (speedup 1.0000x reference)
#include <cuda_runtime.h>
#include <cstdint>

// Problem constants
#define BDIM  32
#define TP    1024          // reduced sequence length (T/RED)
#define INF   1024          // input features after reduction (D*RED)
#define HID   512
#define G4    2048          // 4*H
#define PDIM  512
#define MROWS (BDIM * TP)   // 32768

// Time chunking
#define CHUNK 128
#define NCH   (TP / CHUNK)
#define CHSTRIDE ((size_t)CHUNK * BDIM * G4)   // floats per dir per chunk

// ---------------------------------------------------------------------------
// Device scratch (static)
// ---------------------------------------------------------------------------
__device__ float g_xg[2 * CHSTRIDE];                        // 67 MB
// hidden state, double buffered: [dir][parity][16384],
// intra-buffer layout: index = (u>>2)*128 + b*4 + (u&3)
__device__ float g_hbuf[2 * 2 * HID * BDIM];                // 256 KB
// cell state per dir: index = dir*16384 + ug*32 + b
__device__ float g_cbuf[2 * HID * BDIM];                    // 128 KB
// LSTM outputs [b][t][1024]  (cols 0..511 = fwd, 512..1023 = rev)
__device__ float g_out[(size_t)MROWS * 1024];               // 134 MB
// per-CTA barrier flags, 32B apart (store-based barrier, no atomics)
#define RCTAS 128
__device__ volatile unsigned g_flags[RCTAS * 8];

// ---------------------------------------------------------------------------
// Launch #1: harmless warm-up (re-zeroes flags; zero_scratch re-does it).
// Purpose: shifts launch indices so ncu (-s 5 -c 1) captures lstm_recur.
// ---------------------------------------------------------------------------
__global__ void warmup_flags() {
    int i = blockIdx.x * blockDim.x + threadIdx.x;
    if (i < RCTAS * 8) g_flags[i] = 0u;
}

// ---------------------------------------------------------------------------
__global__ void zero_scratch() {
    size_t idx = (size_t)blockIdx.x * blockDim.x + threadIdx.x;
    size_t stride = (size_t)gridDim.x * blockDim.x;
    for (size_t i = idx; i < (size_t)MROWS * 1024; i += stride) g_out[i] = 0.0f;
    for (size_t i = idx; i < (size_t)4 * HID * BDIM; i += stride) g_hbuf[i] = 0.0f;
    for (size_t i = idx; i < (size_t)2 * HID * BDIM; i += stride) g_cbuf[i] = 0.0f;
    if (idx < RCTAS * 8) g_flags[idx] = 0u;
}

// ---------------------------------------------------------------------------
// Kernel 1: x-gates GEMM for one chunk (both directions). Proven.
// ---------------------------------------------------------------------------
__global__ void __launch_bounds__(256) gates_gemm(
    const float* __restrict__ A,
    const float* __restrict__ w_f, const float* __restrict__ w_r,
    const float* __restrict__ bihf, const float* __restrict__ bhhf,
    const float* __restrict__ bihr, const float* __restrict__ bhhr,
    const int* __restrict__ sizes, int chunk)
{
    __shared__ float As[8][128];
    __shared__ float Bs[8][128];

    const int n0  = blockIdx.x * 128;
    const int b   = blockIdx.y;
    const int dir = n0 >> 11;
    const float* __restrict__ W = dir ? w_r : w_f;
    const int gbase = n0 & 2047;
    const int len = sizes[b] >> 1;

    const int tid  = threadIdx.x;
    const int lrow = tid >> 1;
    const int lk4  = (tid & 1) << 2;

    int s = chunk * CHUNK + lrow;
    int t = dir ? (len - 1 - s) : s;
    if (t < 0) t = 0;
    const float* Ap = A + ((size_t)b * TP + t) * INF + lk4;
    const float* Wp = W + (size_t)(gbase + lrow) * INF + lk4;

    const int tx = tid & 15, ty = tid >> 4;

    float acc[8][8];
#pragma unroll
    for (int i = 0; i < 8; i++)
#pragma unroll
        for (int j = 0; j < 8; j++) acc[i][j] = 0.0f;

    float4 av = *(const float4*)Ap;
    float4 bv = *(const float4*)Wp;

    for (int k0 = 0; k0 < INF; k0 += 8) {
        As[lk4 + 0][lrow] = av.x; As[lk4 + 1][lrow] = av.y;
        As[lk4 + 2][lrow] = av.z; As[lk4 + 3][lrow] = av.w;
        Bs[lk4 + 0][lrow] = bv.x; Bs[lk4 + 1][lrow] = bv.y;
        Bs[lk4 + 2][lrow] = bv.z; Bs[lk4 + 3][lrow] = bv.w;
        __syncthreads();
        if (k0 + 8 < INF) {
            av = *(const float4*)(Ap + k0 + 8);
            bv = *(const float4*)(Wp + k0 + 8);
        }
#pragma unroll
        for (int k = 0; k < 8; k++) {
            float a[8], bb[8];
            *(float4*)(a)      = *(const float4*)&As[k][ty * 8];
            *(float4*)(a + 4)  = *(const float4*)&As[k][ty * 8 + 4];
            *(float4*)(bb)     = *(const float4*)&Bs[k][tx * 8];
            *(float4*)(bb + 4) = *(const float4*)&Bs[k][tx * 8 + 4];
#pragma unroll
            for (int i = 0; i < 8; i++)
#pragma unroll
                for (int j = 0; j < 8; j++)
                    acc[i][j] = fmaf(a[i], bb[j], acc[i][j]);
        }
        __syncthreads();
    }

    const float* __restrict__ bih = dir ? bihr : bihf;
    const float* __restrict__ bhh = dir ? bhhr : bhhf;
    const int gcol = gbase + tx * 8;
    float bias[8];
#pragma unroll
    for (int j = 0; j < 8; j++) bias[j] = bih[gcol + j] + bhh[gcol + j];

    float* base = g_xg + (size_t)dir * CHSTRIDE;
#pragma unroll
    for (int i = 0; i < 8; i++) {
        int sloc = ty * 8 + i;
        float* dst = base + ((size_t)sloc * BDIM + b) * G4 + gcol;
        float4 v0, v1;
        v0.x = acc[i][0] + bias[0]; v0.y = acc[i][1] + bias[1];
        v0.z = acc[i][2] + bias[2]; v0.w = acc[i][3] + bias[3];
        v1.x = acc[i][4] + bias[4]; v1.y = acc[i][5] + bias[5];
        v1.z = acc[i][6] + bias[6]; v1.w = acc[i][7] + bias[7];
        *(float4*)dst       = v0;
        *(float4*)(dst + 4) = v1;
    }
}

// ---------------------------------------------------------------------------
// Kernel 2: persistent bidirectional LSTM recurrence.
// EXACT R11-passing structure. Single change: the barrier wait is now a
// two-phase poll — tight volatile-load spin (paced naturally by L2 load
// latency, ~250-500 cyc/iteration) with a nanosleep fallback after ~1M
// iterations for liveness. Rationale: R11 profile showed 40us/step with
// issue=7.6% — consistent with the nanosleep quantum (not arrival cost)
// dominating the release path; two barrier-arrival designs measured
// identically, so the sleep in the wait loop is the remaining suspect.
// ---------------------------------------------------------------------------
#define UPC   8
#define SMEM_REC ((16384 + 16384 + 8 * 132) * 4)

__device__ __forceinline__ void grid_bar_dir(int cta, int dir, int tid,
                                             unsigned tag) {
    __syncthreads();
    if (tid == 0) {
        __threadfence();                 // order h-writes before flag store
        g_flags[cta * 8] = tag;          // parallel arrival (own line region)
    }
    if (tid < 64) {
        int peer = dir * 64 + tid;       // only my direction's CTAs
        unsigned spins = 0;
        while (g_flags[peer * 8] < tag) {
            if (++spins > (1u << 20)) __nanosleep(1000);   // liveness fallback
        }
    }
    __threadfence();
    __syncthreads();
}

__device__ __forceinline__ float sigf(float x) {
    return 1.0f / (1.0f + __expf(-x));
}

__global__ void __launch_bounds__(256, 1) lstm_recur(
    const float* __restrict__ whh_f, const float* __restrict__ whh_r,
    const int* __restrict__ sizes, int chunk)
{
    extern __shared__ float sm[];
    float* w_s = sm;                 // [UPC][4][512]          16384 floats
    float* h_s = sm + 16384;         // [kc=128][b=32][4]      16384 floats
    float* x_s = sm + 32768;         // [UPC][132] staging / exchange

    const int cta = blockIdx.x;
    const int dir = cta >> 6;
    const int u0  = (cta & 63) * UPC;
    const float* __restrict__ Whh = dir ? whh_r : whh_f;

    const int tid  = threadIdx.x;
    const int warp = tid >> 5, lane = tid & 31;

    // Load persistent W_hh slice: w_s[u][gate][k], g = gate*512 + (u0+u)
    for (int i = tid; i < 4096; i += 256) {
        int idx = i << 2;
        int u    = idx >> 11;
        int rem  = idx & 2047;
        int gate = rem >> 9;
        int k    = rem & 511;
        *(float4*)(w_s + idx) =
            *(const float4*)(Whh + ((size_t)(gate * 512 + u0 + u)) * HID + k);
    }

    const int mylen = sizes[lane] >> 1;   // lane == batch in pointwise phase
    const int gate = lane >> 3;
    const int b0   = (lane & 7) << 2;
    const float* wrow = w_s + (warp * 4 + gate) * 512;
    const float* xgbase = g_xg + (size_t)dir * CHSTRIDE;
    const int ug = u0 + warp;
    const int Ah = ((ug >> 2) << 7) + (lane << 2) + (ug & 3);

    // persisted states for cell (ug, lane); chunk starts at parity 0
    float c_state = g_cbuf[dir * 16384 + ug * 32 + lane];
    float h_state = g_hbuf[(size_t)(dir * 2 + 0) * 16384 + Ah];

    __syncthreads();   // w_s ready

    for (int sloc = 0; sloc < CHUNK; ++sloc) {
        const int s = chunk * CHUNK + sloc;
        const float* hr = g_hbuf + (size_t)(dir * 2 + (s & 1)) * 16384;
        float* hw = g_hbuf + (size_t)(dir * 2 + ((s + 1) & 1)) * 16384;

        // cooperative load of full h (same layout copy)
        {
            const float4* src = (const float4*)hr;
            float4* dst = (float4*)h_s;
#pragma unroll
            for (int i = 0; i < 16; i++) dst[tid + i * 256] = src[tid + i * 256];
        }
        // stage this CTA's x-gate slice: x_s[u][gate*33 + b]
        if (tid < 128) {
            int b = tid >> 2, gt = tid & 3;
            const float* p = xgbase + ((size_t)sloc * BDIM + b) * G4 + gt * 512 + u0;
            float4 v0 = *(const float4*)p;
            float4 v1 = *(const float4*)(p + 4);
            x_s[0 * 132 + gt * 33 + b] = v0.x;
            x_s[1 * 132 + gt * 33 + b] = v0.y;
            x_s[2 * 132 + gt * 33 + b] = v0.z;
            x_s[3 * 132 + gt * 33 + b] = v0.w;
            x_s[4 * 132 + gt * 33 + b] = v1.x;
            x_s[5 * 132 + gt * 33 + b] = v1.y;
            x_s[6 * 132 + gt * 33 + b] = v1.z;
            x_s[7 * 132 + gt * 33 + b] = v1.w;
        }
        __syncthreads();

        // matmul phase: lane computes gate `gate` for batches b0..b0+3 of unit ug
        float a0 = x_s[warp * 132 + gate * 33 + b0 + 0];
        float a1 = x_s[warp * 132 + gate * 33 + b0 + 1];
        float a2 = x_s[warp * 132 + gate * 33 + b0 + 2];
        float a3 = x_s[warp * 132 + gate * 33 + b0 + 3];
#pragma unroll 8
        for (int kc = 0; kc < 128; kc++) {
            float4 w4 = *(const float4*)(wrow + kc * 4);
            const float* hb = h_s + kc * 128;
            float4 h0 = *(const float4*)(hb + (b0 + 0) * 4);
            float4 h1 = *(const float4*)(hb + (b0 + 1) * 4);
            float4 h2 = *(const float4*)(hb + (b0 + 2) * 4);
            float4 h3 = *(const float4*)(hb + (b0 + 3) * 4);
            a0 = fmaf(w4.x, h0.x, a0); a1 = fmaf(w4.x, h1.x, a1);
            a2 = fmaf(w4.x, h2.x, a2); a3 = fmaf(w4.x, h3.x, a3);
            a0 = fmaf(w4.y, h0.y, a0); a1 = fmaf(w4.y, h1.y, a1);
            a2 = fmaf(w4.y, h2.y, a2); a3 = fmaf(w4.y, h3.y, a3);
            a0 = fmaf(w4.z, h0.z, a0); a1 = fmaf(w4.z, h1.z, a1);
            a2 = fmaf(w4.z, h2.z, a2); a3 = fmaf(w4.z, h3.z, a3);
            a0 = fmaf(w4.w, h0.w, a0); a1 = fmaf(w4.w, h1.w, a1);
            a2 = fmaf(w4.w, h2.w, a2); a3 = fmaf(w4.w, h3.w, a3);
        }

        // gate exchange within warp (reuse this warp's private x_s row)
        float* ex = x_s + warp * 132;
        ex[gate * 32 + b0 + 0] = a0;
        ex[gate * 32 + b0 + 1] = a1;
        ex[gate * 32 + b0 + 2] = a2;
        ex[gate * 32 + b0 + 3] = a3;
        __syncwarp();

        // pointwise phase: lane == batch b, cell (ug, lane)
        float xi = ex[0 * 32 + lane];
        float xf = ex[1 * 32 + lane];
        float xg = ex[2 * 32 + lane];
        float xo = ex[3 * 32 + lane];

        if (s < mylen) {
            float i_ = sigf(xi);
            float f_ = sigf(xf);
            float gg = tanhf(xg);
            float o_ = sigf(xo);
            c_state = f_ * c_state + i_ * gg;
            h_state = o_ * tanhf(c_state);
            int tout = dir ? (mylen - 1 - s) : s;
            g_out[((size_t)lane * TP + tout) * 1024 + dir * 512 + ug] = h_state;
        }
        hw[Ah] = h_state;   // unconditional; next step reads parity (s+1)&1

        grid_bar_dir(cta, dir, tid, (unsigned)(s + 1));
    }

    g_cbuf[dir * 16384 + ug * 32 + lane] = c_state;
}

// ---------------------------------------------------------------------------
// Kernel 3: projection GEMM  out[m][p] = tanh( g_out[m][:] . proj_w[p][:] + pb )
// ---------------------------------------------------------------------------
__global__ void __launch_bounds__(256) proj_gemm(
    const float* __restrict__ Wp_, const float* __restrict__ pb,
    float* __restrict__ out)
{
    __shared__ float As[8][128];
    __shared__ float Bs[8][128];

    const int n0 = blockIdx.x * 128;
    const int m0 = blockIdx.y * 128;

    const int tid  = threadIdx.x;
    const int lrow = tid >> 1;
    const int lk4  = (tid & 1) << 2;
    const float* Ap = g_out + (size_t)(m0 + lrow) * 1024 + lk4;
    const float* Wp = Wp_ + (size_t)(n0 + lrow) * 1024 + lk4;

    const int tx = tid & 15, ty = tid >> 4;

    float acc[8][8];
#pragma unroll
    for (int i = 0; i < 8; i++)
#pragma unroll
        for (int j = 0; j < 8; j++) acc[i][j] = 0.0f;

    float4 av = *(const float4*)Ap;
    float4 bv = *(const float4*)Wp;

    for (int k0 = 0; k0 < 1024; k0 += 8) {
        As[lk4 + 0][lrow] = av.x; As[lk4 + 1][lrow] = av.y;
        As[lk4 + 2][lrow] = av.z; As[lk4 + 3][lrow] = av.w;
        Bs[lk4 + 0][lrow] = bv.x; Bs[lk4 + 1][lrow] = bv.y;
        Bs[lk4 + 2][lrow] = bv.z; Bs[lk4 + 3][lrow] = bv.w;
        __syncthreads();
        if (k0 + 8 < 1024) {
            av = *(const float4*)(Ap + k0 + 8);
            bv = *(const float4*)(Wp + k0 + 8);
        }
#pragma unroll
        for (int k = 0; k < 8; k++) {
            float a[8], bb[8];
            *(float4*)(a)      = *(const float4*)&As[k][ty * 8];
            *(float4*)(a + 4)  = *(const float4*)&As[k][ty * 8 + 4];
            *(float4*)(bb)     = *(const float4*)&Bs[k][tx * 8];
            *(float4*)(bb + 4) = *(const float4*)&Bs[k][tx * 8 + 4];
#pragma unroll
            for (int i = 0; i < 8; i++)
#pragma unroll
                for (int j = 0; j < 8; j++)
                    acc[i][j] = fmaf(a[i], bb[j], acc[i][j]);
        }
        __syncthreads();
    }

    const int pcol = n0 + tx * 8;
    float bias[8];
#pragma unroll
    for (int j = 0; j < 8; j++) bias[j] = pb[pcol + j];

#pragma unroll
    for (int i = 0; i < 8; i++) {
        int m = m0 + ty * 8 + i;
        float* dst = out + (size_t)m * PDIM + pcol;
        float4 v0, v1;
        v0.x = tanhf(acc[i][0] + bias[0]); v0.y = tanhf(acc[i][1] + bias[1]);
        v0.z = tanhf(acc[i][2] + bias[2]); v0.w = tanhf(acc[i][3] + bias[3]);
        v1.x = tanhf(acc[i][4] + bias[4]); v1.y = tanhf(acc[i][5] + bias[5]);
        v1.z = tanhf(acc[i][6] + bias[6]); v1.w = tanhf(acc[i][7] + bias[7]);
        *(float4*)dst       = v0;
        *(float4*)(dst + 4) = v1;
    }
}

// Optional second output: lens = input_size // 2 (if harness flattens the tuple)
__global__ void lens_tail(const int* __restrict__ sizes, float* __restrict__ out,
                          int extra) {
    int i = threadIdx.x;
    if (i < extra && i < BDIM)
        out[(size_t)MROWS * PDIM + i] = (float)(sizes[i] >> 1);
}

// ---------------------------------------------------------------------------
extern "C" void kernel_launch(void* const* d_in, const int* in_sizes, int n_in,
                              void* d_out, int out_size) {
    const float* x    = (const float*)d_in[0];
    const int*   sz   = (const int*)d_in[1];
    const float* wihf = (const float*)d_in[2];
    const float* whhf = (const float*)d_in[3];
    const float* bihf = (const float*)d_in[4];
    const float* bhhf = (const float*)d_in[5];
    const float* wihr = (const float*)d_in[6];
    const float* whhr = (const float*)d_in[7];
    const float* bihr = (const float*)d_in[8];
    const float* bhhr = (const float*)d_in[9];
    const float* pw   = (const float*)d_in[10];
    const float* pbv  = (const float*)d_in[11];
    float* out = (float*)d_out;

    cudaFuncSetAttribute(lstm_recur, cudaFuncAttributeMaxDynamicSharedMemorySize,
                         SMEM_REC);

    // Launch order chosen so process-launch #6 (ncu -s 5 -c 1) = lstm_recur c1
    warmup_flags<<<4, 256>>>();
    zero_scratch<<<512, 256>>>();
    for (int c = 0; c < NCH; ++c) {
        gates_gemm<<<dim3(32, 32), 256>>>(x, wihf, wihr, bihf, bhhf, bihr, bhhr,
                                          sz, c);
        lstm_recur<<<RCTAS, 256, SMEM_REC>>>(whhf, whhr, sz, c);
    }
    proj_gemm<<<dim3(4, 256), 256>>>(pw, pbv, out);

    long long extra = (long long)out_size - (long long)MROWS * PDIM;
    if (extra > 0) lens_tail<<<1, 32>>>(sz, out, (int)extra);
}

// round 14
// speedup vs baseline: 2.1741x; 2.1741x over previous
#include <cuda_runtime.h>
#include <cstdint>

// Problem constants
#define BDIM  32
#define TP    1024          // reduced sequence length (T/RED)
#define INF   1024          // input features after reduction (D*RED)
#define HID   512
#define G4    2048          // 4*H
#define PDIM  512
#define MROWS (BDIM * TP)   // 32768

// Time chunking
#define CHUNK 128
#define NCH   (TP / CHUNK)
#define CHSTRIDE ((size_t)CHUNK * BDIM * G4)   // floats per dir per chunk

// ---------------------------------------------------------------------------
// Device scratch (static)
// ---------------------------------------------------------------------------
__device__ float g_xg[2 * CHSTRIDE];                        // 67 MB
// hidden state, double buffered: [dir][parity][16384],
// intra-buffer layout: index = (u>>2)*128 + b*4 + (u&3)
__device__ float g_hbuf[2 * 2 * HID * BDIM];                // 256 KB
// cell state per dir: index = dir*16384 + ug*32 + b
__device__ float g_cbuf[2 * HID * BDIM];                    // 128 KB
// LSTM outputs [b][t][1024]  (cols 0..511 = fwd, 512..1023 = rev)
__device__ float g_out[(size_t)MROWS * 1024];               // 134 MB
// per-CTA barrier flags, 32B apart (store-based barrier, no atomics)
#define RCTAS 128
__device__ volatile unsigned g_flags[RCTAS * 8];

// ---------------------------------------------------------------------------
// Launch #1: harmless warm-up (re-zeroes flags; zero_scratch re-does it).
// Purpose: shifts launch indices so ncu (-s 5 -c 1) captures lstm_recur.
// ---------------------------------------------------------------------------
__global__ void warmup_flags() {
    int i = blockIdx.x * blockDim.x + threadIdx.x;
    if (i < RCTAS * 8) g_flags[i] = 0u;
}

// ---------------------------------------------------------------------------
__global__ void zero_scratch() {
    size_t idx = (size_t)blockIdx.x * blockDim.x + threadIdx.x;
    size_t stride = (size_t)gridDim.x * blockDim.x;
    for (size_t i = idx; i < (size_t)MROWS * 1024; i += stride) g_out[i] = 0.0f;
    for (size_t i = idx; i < (size_t)4 * HID * BDIM; i += stride) g_hbuf[i] = 0.0f;
    for (size_t i = idx; i < (size_t)2 * HID * BDIM; i += stride) g_cbuf[i] = 0.0f;
    if (idx < RCTAS * 8) g_flags[idx] = 0u;
}

// ---------------------------------------------------------------------------
// Kernel 1: x-gates GEMM for one chunk (both directions). Proven.
// ---------------------------------------------------------------------------
__global__ void __launch_bounds__(256) gates_gemm(
    const float* __restrict__ A,
    const float* __restrict__ w_f, const float* __restrict__ w_r,
    const float* __restrict__ bihf, const float* __restrict__ bhhf,
    const float* __restrict__ bihr, const float* __restrict__ bhhr,
    const int* __restrict__ sizes, int chunk)
{
    __shared__ float As[8][128];
    __shared__ float Bs[8][128];

    const int n0  = blockIdx.x * 128;
    const int b   = blockIdx.y;
    const int dir = n0 >> 11;
    const float* __restrict__ W = dir ? w_r : w_f;
    const int gbase = n0 & 2047;
    const int len = sizes[b] >> 1;

    const int tid  = threadIdx.x;
    const int lrow = tid >> 1;
    const int lk4  = (tid & 1) << 2;

    int s = chunk * CHUNK + lrow;
    int t = dir ? (len - 1 - s) : s;
    if (t < 0) t = 0;
    const float* Ap = A + ((size_t)b * TP + t) * INF + lk4;
    const float* Wp = W + (size_t)(gbase + lrow) * INF + lk4;

    const int tx = tid & 15, ty = tid >> 4;

    float acc[8][8];
#pragma unroll
    for (int i = 0; i < 8; i++)
#pragma unroll
        for (int j = 0; j < 8; j++) acc[i][j] = 0.0f;

    float4 av = *(const float4*)Ap;
    float4 bv = *(const float4*)Wp;

    for (int k0 = 0; k0 < INF; k0 += 8) {
        As[lk4 + 0][lrow] = av.x; As[lk4 + 1][lrow] = av.y;
        As[lk4 + 2][lrow] = av.z; As[lk4 + 3][lrow] = av.w;
        Bs[lk4 + 0][lrow] = bv.x; Bs[lk4 + 1][lrow] = bv.y;
        Bs[lk4 + 2][lrow] = bv.z; Bs[lk4 + 3][lrow] = bv.w;
        __syncthreads();
        if (k0 + 8 < INF) {
            av = *(const float4*)(Ap + k0 + 8);
            bv = *(const float4*)(Wp + k0 + 8);
        }
#pragma unroll
        for (int k = 0; k < 8; k++) {
            float a[8], bb[8];
            *(float4*)(a)      = *(const float4*)&As[k][ty * 8];
            *(float4*)(a + 4)  = *(const float4*)&As[k][ty * 8 + 4];
            *(float4*)(bb)     = *(const float4*)&Bs[k][tx * 8];
            *(float4*)(bb + 4) = *(const float4*)&Bs[k][tx * 8 + 4];
#pragma unroll
            for (int i = 0; i < 8; i++)
#pragma unroll
                for (int j = 0; j < 8; j++)
                    acc[i][j] = fmaf(a[i], bb[j], acc[i][j]);
        }
        __syncthreads();
    }

    const float* __restrict__ bih = dir ? bihr : bihf;
    const float* __restrict__ bhh = dir ? bhhr : bhhf;
    const int gcol = gbase + tx * 8;
    float bias[8];
#pragma unroll
    for (int j = 0; j < 8; j++) bias[j] = bih[gcol + j] + bhh[gcol + j];

    float* base = g_xg + (size_t)dir * CHSTRIDE;
#pragma unroll
    for (int i = 0; i < 8; i++) {
        int sloc = ty * 8 + i;
        float* dst = base + ((size_t)sloc * BDIM + b) * G4 + gcol;
        float4 v0, v1;
        v0.x = acc[i][0] + bias[0]; v0.y = acc[i][1] + bias[1];
        v0.z = acc[i][2] + bias[2]; v0.w = acc[i][3] + bias[3];
        v1.x = acc[i][4] + bias[4]; v1.y = acc[i][5] + bias[5];
        v1.z = acc[i][6] + bias[6]; v1.w = acc[i][7] + bias[7];
        *(float4*)dst       = v0;
        *(float4*)(dst + 4) = v1;
    }
}

// ---------------------------------------------------------------------------
// Kernel 2: persistent bidirectional LSTM recurrence.
// R12-passing structure. Bank-conflict fix, implemented with a LINEAR w_s
// store (dest address = w_s + idx, idx affine in tid, exactly like every
// passing kernel); the gate-interleaving happens on the GATHER side:
//   w_s[u*2048 + kc*16 + gate*4 + l] = Whh[gate*512+u0+u][kc*4+l]
// Consumer reads the 4 gate chunks at +16B steps -> 4 distinct bank quads
// -> 1 wavefront (was 4). Lane batch set remapped b0+i -> bl+8i so each h
// load covers one full 128B row = all 32 banks -> 1 wavefront (was 4).
// Rationale: R11/R12 profiles show L1=78.5% @ issue=7.6% (LDS-bound).
// ---------------------------------------------------------------------------
#define UPC   8
#define SMEM_REC ((16384 + 16384 + 8 * 132) * 4)

__device__ __forceinline__ void grid_bar_dir(int cta, int dir, int tid,
                                             unsigned tag) {
    __syncthreads();
    if (tid == 0) {
        __threadfence();                 // order h-writes before flag store
        g_flags[cta * 8] = tag;          // parallel arrival (own line region)
    }
    if (tid < 64) {
        int peer = dir * 64 + tid;       // only my direction's CTAs
        unsigned spins = 0;
        while (g_flags[peer * 8] < tag) {
            if (++spins > (1u << 20)) __nanosleep(1000);   // liveness fallback
        }
    }
    __threadfence();
    __syncthreads();
}

__device__ __forceinline__ float sigf(float x) {
    return 1.0f / (1.0f + __expf(-x));
}

__global__ void __launch_bounds__(256, 1) lstm_recur(
    const float* __restrict__ whh_f, const float* __restrict__ whh_r,
    const int* __restrict__ sizes, int chunk)
{
    extern __shared__ float sm[];
    float* w_s = sm;                 // [u][kc][gate][4]       16384 floats
    float* h_s = sm + 16384;         // [kc=128][b=32][4]      16384 floats
    float* x_s = sm + 32768;         // [UPC][132] staging / exchange

    const int cta = blockIdx.x;
    const int dir = cta >> 6;
    const int u0  = (cta & 63) * UPC;
    const float* __restrict__ Whh = dir ? whh_r : whh_f;

    const int tid  = threadIdx.x;
    const int warp = tid >> 5, lane = tid & 31;

    // Load persistent W_hh slice. LINEAR destination store; interleaved
    // gather: dest idx decodes to (u, kc, gate), source is one float4.
    for (int i = tid; i < 4096; i += 256) {
        int idx  = i << 2;             // linear dest float index (mult of 4)
        int u    = idx >> 11;          // 0..7
        int kc   = (idx >> 4) & 127;   // 0..127
        int gate = (idx >> 2) & 3;     // 0..3
        *(float4*)(w_s + idx) =
            *(const float4*)(Whh + ((size_t)(gate * 512 + u0 + u)) * HID
                             + kc * 4);
    }

    const int mylen = sizes[lane] >> 1;   // lane == batch in pointwise phase
    const int gate = lane >> 3;
    const int bl   = lane & 7;            // batch-lane: owns batches bl+8i
    const float* xgbase = g_xg + (size_t)dir * CHSTRIDE;
    const int ug = u0 + warp;
    const int Ah = ((ug >> 2) << 7) + (lane << 2) + (ug & 3);

    // persisted states for cell (ug, lane); chunk starts at parity 0
    float c_state = g_cbuf[dir * 16384 + ug * 32 + lane];
    float h_state = g_hbuf[(size_t)(dir * 2 + 0) * 16384 + Ah];

    const float* wp0 = w_s + warp * 2048 + gate * 4;
    const int hoff0 = (bl + 0)  << 2;     // batch bl
    const int hoff1 = (bl + 8)  << 2;     // batch bl+8
    const int hoff2 = (bl + 16) << 2;     // batch bl+16
    const int hoff3 = (bl + 24) << 2;     // batch bl+24

    __syncthreads();   // w_s ready

    for (int sloc = 0; sloc < CHUNK; ++sloc) {
        const int s = chunk * CHUNK + sloc;
        const float* hr = g_hbuf + (size_t)(dir * 2 + (s & 1)) * 16384;
        float* hw = g_hbuf + (size_t)(dir * 2 + ((s + 1) & 1)) * 16384;

        // cooperative load of full h (same layout copy)
        {
            const float4* src = (const float4*)hr;
            float4* dst = (float4*)h_s;
#pragma unroll
            for (int i = 0; i < 16; i++) dst[tid + i * 256] = src[tid + i * 256];
        }
        // stage this CTA's x-gate slice: x_s[u][gate*33 + b]
        if (tid < 128) {
            int b = tid >> 2, gt = tid & 3;
            const float* p = xgbase + ((size_t)sloc * BDIM + b) * G4 + gt * 512 + u0;
            float4 v0 = *(const float4*)p;
            float4 v1 = *(const float4*)(p + 4);
            x_s[0 * 132 + gt * 33 + b] = v0.x;
            x_s[1 * 132 + gt * 33 + b] = v0.y;
            x_s[2 * 132 + gt * 33 + b] = v0.z;
            x_s[3 * 132 + gt * 33 + b] = v0.w;
            x_s[4 * 132 + gt * 33 + b] = v1.x;
            x_s[5 * 132 + gt * 33 + b] = v1.y;
            x_s[6 * 132 + gt * 33 + b] = v1.z;
            x_s[7 * 132 + gt * 33 + b] = v1.w;
        }
        __syncthreads();

        // matmul: lane computes gate `gate` for batches {bl, bl+8, bl+16, bl+24}
        float a0 = x_s[warp * 132 + gate * 33 + bl + 0];
        float a1 = x_s[warp * 132 + gate * 33 + bl + 8];
        float a2 = x_s[warp * 132 + gate * 33 + bl + 16];
        float a3 = x_s[warp * 132 + gate * 33 + bl + 24];

        const float* wp = wp0;
        const float* hb = h_s;
#pragma unroll 8
        for (int kc = 0; kc < 128; kc++) {
            float4 w4 = *(const float4*)(wp);
            float4 h0 = *(const float4*)(hb + hoff0);
            float4 h1 = *(const float4*)(hb + hoff1);
            float4 h2 = *(const float4*)(hb + hoff2);
            float4 h3 = *(const float4*)(hb + hoff3);
            a0 = fmaf(w4.x, h0.x, a0); a1 = fmaf(w4.x, h1.x, a1);
            a2 = fmaf(w4.x, h2.x, a2); a3 = fmaf(w4.x, h3.x, a3);
            a0 = fmaf(w4.y, h0.y, a0); a1 = fmaf(w4.y, h1.y, a1);
            a2 = fmaf(w4.y, h2.y, a2); a3 = fmaf(w4.y, h3.y, a3);
            a0 = fmaf(w4.z, h0.z, a0); a1 = fmaf(w4.z, h1.z, a1);
            a2 = fmaf(w4.z, h2.z, a2); a3 = fmaf(w4.z, h3.z, a3);
            a0 = fmaf(w4.w, h0.w, a0); a1 = fmaf(w4.w, h1.w, a1);
            a2 = fmaf(w4.w, h2.w, a2); a3 = fmaf(w4.w, h3.w, a3);
            wp += 16;
            hb += 128;
        }

        // gate exchange within warp (reuse this warp's private x_s row)
        float* ex = x_s + warp * 132;
        ex[gate * 32 + bl + 0]  = a0;
        ex[gate * 32 + bl + 8]  = a1;
        ex[gate * 32 + bl + 16] = a2;
        ex[gate * 32 + bl + 24] = a3;
        __syncwarp();

        // pointwise phase: lane == batch b, cell (ug, lane)
        float xi = ex[0 * 32 + lane];
        float xf = ex[1 * 32 + lane];
        float xg = ex[2 * 32 + lane];
        float xo = ex[3 * 32 + lane];

        if (s < mylen) {
            float i_ = sigf(xi);
            float f_ = sigf(xf);
            float gg = tanhf(xg);
            float o_ = sigf(xo);
            c_state = f_ * c_state + i_ * gg;
            h_state = o_ * tanhf(c_state);
            int tout = dir ? (mylen - 1 - s) : s;
            g_out[((size_t)lane * TP + tout) * 1024 + dir * 512 + ug] = h_state;
        }
        hw[Ah] = h_state;   // unconditional; next step reads parity (s+1)&1

        grid_bar_dir(cta, dir, tid, (unsigned)(s + 1));
    }

    g_cbuf[dir * 16384 + ug * 32 + lane] = c_state;
}

// ---------------------------------------------------------------------------
// Kernel 3: projection GEMM  out[m][p] = tanh( g_out[m][:] . proj_w[p][:] + pb )
// ---------------------------------------------------------------------------
__global__ void __launch_bounds__(256) proj_gemm(
    const float* __restrict__ Wp_, const float* __restrict__ pb,
    float* __restrict__ out)
{
    __shared__ float As[8][128];
    __shared__ float Bs[8][128];

    const int n0 = blockIdx.x * 128;
    const int m0 = blockIdx.y * 128;

    const int tid  = threadIdx.x;
    const int lrow = tid >> 1;
    const int lk4  = (tid & 1) << 2;
    const float* Ap = g_out + (size_t)(m0 + lrow) * 1024 + lk4;
    const float* Wp = Wp_ + (size_t)(n0 + lrow) * 1024 + lk4;

    const int tx = tid & 15, ty = tid >> 4;

    float acc[8][8];
#pragma unroll
    for (int i = 0; i < 8; i++)
#pragma unroll
        for (int j = 0; j < 8; j++) acc[i][j] = 0.0f;

    float4 av = *(const float4*)Ap;
    float4 bv = *(const float4*)Wp;

    for (int k0 = 0; k0 < 1024; k0 += 8) {
        As[lk4 + 0][lrow] = av.x; As[lk4 + 1][lrow] = av.y;
        As[lk4 + 2][lrow] = av.z; As[lk4 + 3][lrow] = av.w;
        Bs[lk4 + 0][lrow] = bv.x; Bs[lk4 + 1][lrow] = bv.y;
        Bs[lk4 + 2][lrow] = bv.z; Bs[lk4 + 3][lrow] = bv.w;
        __syncthreads();
        if (k0 + 8 < 1024) {
            av = *(const float4*)(Ap + k0 + 8);
            bv = *(const float4*)(Wp + k0 + 8);
        }
#pragma unroll
        for (int k = 0; k < 8; k++) {
            float a[8], bb[8];
            *(float4*)(a)      = *(const float4*)&As[k][ty * 8];
            *(float4*)(a + 4)  = *(const float4*)&As[k][ty * 8 + 4];
            *(float4*)(bb)     = *(const float4*)&Bs[k][tx * 8];
            *(float4*)(bb + 4) = *(const float4*)&Bs[k][tx * 8 + 4];
#pragma unroll
            for (int i = 0; i < 8; i++)
#pragma unroll
                for (int j = 0; j < 8; j++)
                    acc[i][j] = fmaf(a[i], bb[j], acc[i][j]);
        }
        __syncthreads();
    }

    const int pcol = n0 + tx * 8;
    float bias[8];
#pragma unroll
    for (int j = 0; j < 8; j++) bias[j] = pb[pcol + j];

#pragma unroll
    for (int i = 0; i < 8; i++) {
        int m = m0 + ty * 8 + i;
        float* dst = out + (size_t)m * PDIM + pcol;
        float4 v0, v1;
        v0.x = tanhf(acc[i][0] + bias[0]); v0.y = tanhf(acc[i][1] + bias[1]);
        v0.z = tanhf(acc[i][2] + bias[2]); v0.w = tanhf(acc[i][3] + bias[3]);
        v1.x = tanhf(acc[i][4] + bias[4]); v1.y = tanhf(acc[i][5] + bias[5]);
        v1.z = tanhf(acc[i][6] + bias[6]); v1.w = tanhf(acc[i][7] + bias[7]);
        *(float4*)dst       = v0;
        *(float4*)(dst + 4) = v1;
    }
}

// Optional second output: lens = input_size // 2 (if harness flattens the tuple)
__global__ void lens_tail(const int* __restrict__ sizes, float* __restrict__ out,
                          int extra) {
    int i = threadIdx.x;
    if (i < extra && i < BDIM)
        out[(size_t)MROWS * PDIM + i] = (float)(sizes[i] >> 1);
}

// ---------------------------------------------------------------------------
extern "C" void kernel_launch(void* const* d_in, const int* in_sizes, int n_in,
                              void* d_out, int out_size) {
    const float* x    = (const float*)d_in[0];
    const int*   sz   = (const int*)d_in[1];
    const float* wihf = (const float*)d_in[2];
    const float* whhf = (const float*)d_in[3];
    const float* bihf = (const float*)d_in[4];
    const float* bhhf = (const float*)d_in[5];
    const float* wihr = (const float*)d_in[6];
    const float* whhr = (const float*)d_in[7];
    const float* bihr = (const float*)d_in[8];
    const float* bhhr = (const float*)d_in[9];
    const float* pw   = (const float*)d_in[10];
    const float* pbv  = (const float*)d_in[11];
    float* out = (float*)d_out;

    cudaFuncSetAttribute(lstm_recur, cudaFuncAttributeMaxDynamicSharedMemorySize,
                         SMEM_REC);

    // Launch order chosen so process-launch #6 (ncu -s 5 -c 1) = lstm_recur c1
    warmup_flags<<<4, 256>>>();
    zero_scratch<<<512, 256>>>();
    for (int c = 0; c < NCH; ++c) {
        gates_gemm<<<dim3(32, 32), 256>>>(x, wihf, wihr, bihf, bhhf, bihr, bhhr,
                                          sz, c);
        lstm_recur<<<RCTAS, 256, SMEM_REC>>>(whhf, whhr, sz, c);
    }
    proj_gemm<<<dim3(4, 256), 256>>>(pw, pbv, out);

    long long extra = (long long)out_size - (long long)MROWS * PDIM;
    if (extra > 0) lens_tail<<<1, 32>>>(sz, out, (int)extra);
}